// round 13
// baseline (speedup 1.0000x reference)
#include <cuda_runtime.h>
#include <cuda_bf16.h>
#include <cstdint>

// Problem constants
#define B_      32
#define C_      512
#define HW_     4096            // 64*64
#define NPIX    (B_ * HW_)      // 131072
#define M_      1024
#define THRESH  0.8f
#define MSCALE  16.0f           // fp8 scale applied to normalized memory rows

// ---------------------------------------------------------------------------
// Device scratch (no cudaMalloc allowed)
// ---------------------------------------------------------------------------
__device__ uint8_t g_mem8[M_ * C_];     // normalized memory * 16, e4m3

__device__ __forceinline__ uint32_t smem_u32(const void* p) {
    uint32_t a;
    asm("{ .reg .u64 t; cvta.to.shared.u64 t, %1; cvt.u32.u64 %0, t; }" : "=r"(a) : "l"(p));
    return a;
}

__device__ __forceinline__ void ldsm_x4(uint32_t* r, uint32_t addr) {
    asm volatile("ldmatrix.sync.aligned.m8n8.x4.shared.b16 {%0,%1,%2,%3}, [%4];"
        : "=r"(r[0]), "=r"(r[1]), "=r"(r[2]), "=r"(r[3]) : "r"(addr));
}

__device__ __forceinline__ void mma_fp8(float* d, const uint32_t* a, const uint32_t* b) {
    asm volatile("mma.sync.aligned.m16n8k32.row.col.f32.e4m3.e4m3.f32 "
        "{%0,%1,%2,%3}, {%4,%5,%6,%7}, {%8,%9}, {%0,%1,%2,%3};"
        : "+f"(d[0]), "+f"(d[1]), "+f"(d[2]), "+f"(d[3])
        : "r"(a[0]), "r"(a[1]), "r"(a[2]), "r"(a[3]), "r"(b[0]), "r"(b[1]));
}

// pack 2 floats -> 2 e4m3 bytes (same helper for x and memory: consistent
// k-permutation, dot-invariant).
__device__ __forceinline__ uint16_t pk2(float lo, float hi) {
    uint16_t r;
    asm("cvt.rn.satfinite.e4m3x2.f32 %0, %1, %2;" : "=h"(r) : "f"(hi), "f"(lo));
    return r;
}

__device__ __forceinline__ void cp16(uint32_t dst, const void* src) {
    asm volatile("cp.async.cg.shared.global [%0], [%1], 16;" :: "r"(dst), "l"(src));
}
#define CP_COMMIT() asm volatile("cp.async.commit_group;" ::: "memory")
#define CP_WAIT0()  asm volatile("cp.async.wait_group 0;" ::: "memory")

// ---------------------------------------------------------------------------
// Kernel 0: normalize memory rows -> e4m3 (scaled by 16)
// ---------------------------------------------------------------------------
__global__ void norm_mem_kernel(const float* __restrict__ mem) {
    int row = blockIdx.x;
    int t   = threadIdx.x;   // 128 threads, 4 floats each
    const float4* r = (const float4*)(mem + (size_t)row * C_);
    float4 v = r[t];
    float ss = v.x * v.x + v.y * v.y + v.z * v.z + v.w * v.w;
#pragma unroll
    for (int o = 16; o; o >>= 1) ss += __shfl_xor_sync(0xffffffffu, ss, o);
    __shared__ float ws[4];
    if ((t & 31) == 0) ws[t >> 5] = ss;
    __syncthreads();
    float tot = ws[0] + ws[1] + ws[2] + ws[3];
    float inv = MSCALE / fmaxf(sqrtf(tot), 1e-12f);
    uint16_t a = pk2(v.x * inv, v.y * inv);
    uint16_t b = pk2(v.z * inv, v.w * inv);
    ((uint32_t*)(g_mem8 + (size_t)row * C_))[t] = (uint32_t)a | ((uint32_t)b << 16);
}

// ---------------------------------------------------------------------------
// Kernel 1: FULLY FUSED fp8 pipeline, 4 CTAs/SM.
// CTA = 256 threads (8 warps) = 64 pixels (one b, 64 consecutive hw).
// A (64px x 512K e4m3) SMEM-resident, pitch 528 B. Loop 8 N-tiles of 128
// memory rows; B streamed in k=64 fp8 chunks (128 rows x 64 B, pitch 80),
// double-buffered via cp.async; chunk 0 preloads under the whole prologue.
// Warp tile 32px x 32m: per k32 step 2+2 LDSM.x4 -> 8 QMMA.
// Fused argmax + masked channel-major STG.128 output.
// ---------------------------------------------------------------------------
#define A_PITCH    528
#define B_PITCH    80
#define OFF_B      33792         // 64 * 528
#define B_CHUNK    10240         // 128 * 80
#define OFF_REDV   54272         // OFF_B + 2*B_CHUNK
#define OFF_REDI   55296
#define OFF_PN     56320         // 64 floats
#define OFF_SEL    56576         // 64 ints
#define SMEM_BYTES 56832

__global__ __launch_bounds__(256, 4) void sim_fused_kernel(
    const float* __restrict__ x,
    const float* __restrict__ memf,
    float* __restrict__ out
) {
    extern __shared__ char smem[];
    uint32_t sb = smem_u32(smem);
    float* redv = (float*)(smem + OFF_REDV);   // [64][4]
    int*   redi = (int*)(smem + OFF_REDI);     // [64][4]
    float* pn   = (float*)(smem + OFF_PN);     // [64]
    int*   ssel = (int*)(smem + OFF_SEL);      // [64]

    int t    = threadIdx.x;
    int lane = t & 31;
    int w    = t >> 5;
    int wr   = w & 1;      // pixel half (32 px)
    int wc   = w >> 1;     // m quarter (32 m)
    int pix0 = blockIdx.x * 64;
    int b    = pix0 >> 12;
    int hw0  = pix0 & (HW_ - 1);

    // B chunk loader via cp.async: rows nt*128..+127, k bytes kc*64..+63
    auto loadB = [&](int nt, int kc, int buf) {
        const char* bsrc = (const char*)g_mem8 + (size_t)(nt * 128) * C_ + kc * 64;
        uint32_t bbm = sb + OFF_B + (uint32_t)buf * B_CHUNK;
#pragma unroll
        for (int i = 0; i < 2; i++) {
            int idx = t + i * 256;           // 0..511 quads (4 per row)
            int m = idx >> 2;
            int q = idx & 3;
            cp16(bbm + (uint32_t)(m * B_PITCH + q * 16),
                 bsrc + (size_t)m * C_ + q * 16);
        }
        CP_COMMIT();
    };

    // ---- preload B chunk 0 into buf0; it flies under the whole prologue ----
    loadB(0, 0, 0);

    // ================= PROLOGUE: x -> A tile (transpose + e4m3 + norm) =====
    // Staging lives in B buf1 (10240 B >= 32*65*4 = 8320 B): 32 channels/iter.
    {
        float* stage = (float*)(smem + OFF_B + B_CHUNK);   // [32][65] floats
        int hwi = t & 63;
        int cl  = t >> 6;              // 0..3
        int px  = t >> 2;              // 0..63
        int sl  = t & 3;               // 8-channel slice within 32-c sub-tile
        float ss = 0.f;
        const float* xb = x + (size_t)b * C_ * HW_ + hw0;

        for (int h = 0; h < 16; h++) {        // 32 channels per iteration
            const float* src = xb + (size_t)(h * 32) * HW_;
#pragma unroll
            for (int i = 0; i < 8; i++) {
                stage[(cl + i * 4) * 65 + hwi] = src[(size_t)(cl + i * 4) * HW_ + hwi];
            }
            __syncthreads();
            uint16_t h4[4];
#pragma unroll
            for (int j = 0; j < 4; j++) {
                float a  = stage[(sl * 8 + 2 * j) * 65 + px];
                float c2 = stage[(sl * 8 + 2 * j + 1) * 65 + px];
                ss += a * a + c2 * c2;
                h4[j] = pk2(a, c2);
            }
            uint2 r2;
            r2.x = (uint32_t)h4[0] | ((uint32_t)h4[1] << 16);
            r2.y = (uint32_t)h4[2] | ((uint32_t)h4[3] << 16);
            *(uint2*)(smem + px * A_PITCH + h * 32 + sl * 8) = r2;
            __syncthreads();
        }
        ss += __shfl_xor_sync(0xffffffffu, ss, 1);
        ss += __shfl_xor_sync(0xffffffffu, ss, 2);
        if (sl == 0) pn[px] = ss;
    }

    // ================= MAINLOOP: fp8 QMMA GEMM + argmax =====================
    uint32_t aAddr[2];
#pragma unroll
    for (int i = 0; i < 2; i++)
        aAddr[i] = sb + (uint32_t)(wr * 32 + i * 16 + (lane & 15)) * A_PITCH
                      + (uint32_t)(lane >> 4) * 16u;
    uint32_t bAddr[2];
#pragma unroll
    for (int jp = 0; jp < 2; jp++)
        bAddr[jp] = sb + OFF_B
                  + (uint32_t)(wc * 32 + (2 * jp + (lane >> 4)) * 8 + (lane & 7)) * B_PITCH
                  + (uint32_t)((lane >> 3) & 1) * 16u;

    float bestv[2][2];
    int   besti[2][2];
#pragma unroll
    for (int i = 0; i < 2; i++) {
        bestv[i][0] = -1e30f; bestv[i][1] = -1e30f;
        besti[i][0] = 0;      besti[i][1] = 0;
    }

    for (int nt = 0; nt < 8; nt++) {
        float acc[2][4][4];
#pragma unroll
        for (int i = 0; i < 2; i++)
#pragma unroll
            for (int j = 0; j < 4; j++)
#pragma unroll
                for (int r = 0; r < 4; r++) acc[i][j][r] = 0.f;

        for (int kc = 0; kc < 8; kc++) {          // 8 chunks of k=64
            CP_WAIT0();        // chunk kc fully arrived
            __syncthreads();   // visible everywhere; compute(kc-1) done
            {
                int nkc = kc + 1, nnt = nt;
                if (nkc == 8) { nkc = 0; nnt = nt + 1; }
                if (nnt < 8) loadB(nnt, nkc, (kc + 1) & 1);
            }
            uint32_t bufOff = (uint32_t)((kc & 1) * B_CHUNK);
            uint32_t kcOff  = (uint32_t)(kc * 64);    // 64 fp8 bytes per chunk
#pragma unroll
            for (int ks = 0; ks < 2; ks++) {
                uint32_t ko = (uint32_t)(ks * 32);    // 32 fp8 = one k32 step
                uint32_t af[2][4];
#pragma unroll
                for (int i = 0; i < 2; i++)
                    ldsm_x4(af[i], aAddr[i] + kcOff + ko);
                uint32_t bfr[2][4];
#pragma unroll
                for (int jp = 0; jp < 2; jp++)
                    ldsm_x4(bfr[jp], bAddr[jp] + bufOff + ko);
#pragma unroll
                for (int i = 0; i < 2; i++)
#pragma unroll
                    for (int j = 0; j < 4; j++)
                        mma_fp8(acc[i][j], af[i], &bfr[j >> 1][(j & 1) * 2]);
            }
        }

        // fold N-tile into running argmax (first-max tie-break)
#pragma unroll
        for (int i = 0; i < 2; i++)
#pragma unroll
            for (int rp = 0; rp < 2; rp++)
#pragma unroll
                for (int j = 0; j < 4; j++)
#pragma unroll
                    for (int c = 0; c < 2; c++) {
                        float v = acc[i][j][rp * 2 + c];
                        if (v > bestv[i][rp]) {
                            bestv[i][rp] = v;
                            besti[i][rp] = nt * 128 + wc * 32 + j * 8 + (lane & 3) * 2 + c;
                        }
                    }
    }

    // ================= EPILOGUE: reductions + selection =====================
#pragma unroll
    for (int i = 0; i < 2; i++)
#pragma unroll
        for (int rp = 0; rp < 2; rp++) {
            float v = bestv[i][rp];
            int   ix = besti[i][rp];
#pragma unroll
            for (int off = 1; off <= 2; off <<= 1) {
                float ov = __shfl_xor_sync(0xffffffffu, v, off);
                int   oi = __shfl_xor_sync(0xffffffffu, ix, off);
                if (ov > v || (ov == v && oi < ix)) { v = ov; ix = oi; }
            }
            if ((lane & 3) == 0) {
                int row = wr * 32 + i * 16 + (lane >> 2) + rp * 8;
                redv[row * 4 + wc] = v;
                redi[row * 4 + wc] = ix;
            }
        }
    __syncthreads();
    if (t < 64) {
        float bv = redv[t * 4];
        int   bi = redi[t * 4];
#pragma unroll
        for (int j = 1; j < 4; j++) {
            float v = redv[t * 4 + j];
            if (v > bv) { bv = v; bi = redi[t * 4 + j]; }
        }
        float n2 = pn[t];
        // dot_q ~ 16 * (x . m_hat); fire iff dot_q > 0.8 * 16 * ||x||
        ssel[t] = (bv > (THRESH * MSCALE) * sqrtf(n2)) ? bi : -1;
    }
    __syncthreads();

    // ================= OUTPUT: masked gather, channel-major STG.128 =========
    {
        int q4 = (t & 15) * 4;           // pixel quad
        int c0 = t >> 4;                 // 0..15
        int s0 = ssel[q4 + 0];
        int s1 = ssel[q4 + 1];
        int s2 = ssel[q4 + 2];
        int s3 = ssel[q4 + 3];
        const float* mr0 = memf + (size_t)(s0 < 0 ? 0 : s0) * C_;
        const float* mr1 = memf + (size_t)(s1 < 0 ? 0 : s1) * C_;
        const float* mr2 = memf + (size_t)(s2 < 0 ? 0 : s2) * C_;
        const float* mr3 = memf + (size_t)(s3 < 0 ? 0 : s3) * C_;
        float* ob = out + ((size_t)b * C_) * HW_ + hw0 + q4;
#pragma unroll 8
        for (int i = 0; i < 32; i++) {
            int c = c0 + i * 16;
            float4 v;
            v.x = (s0 >= 0) ? mr0[c] : 0.f;
            v.y = (s1 >= 0) ? mr1[c] : 0.f;
            v.z = (s2 >= 0) ? mr2[c] : 0.f;
            v.w = (s3 >= 0) ? mr3[c] : 0.f;
            *(float4*)(ob + (size_t)c * HW_) = v;
        }
    }
}

// ---------------------------------------------------------------------------
extern "C" void kernel_launch(void* const* d_in, const int* in_sizes, int n_in,
                              void* d_out, int out_size) {
    const float* x   = (const float*)d_in[0];   // 32*512*64*64
    const float* mem = (const float*)d_in[1];   // 1024*512
    float* out = (float*)d_out;

    cudaFuncSetAttribute(sim_fused_kernel,
                         cudaFuncAttributeMaxDynamicSharedMemorySize, SMEM_BYTES);

    norm_mem_kernel<<<M_, 128>>>(mem);
    sim_fused_kernel<<<NPIX / 64, 256, SMEM_BYTES>>>(x, mem, out);
}

// round 14
// speedup vs baseline: 1.3203x; 1.3203x over previous
#include <cuda_runtime.h>
#include <cuda_bf16.h>
#include <cstdint>

// Problem constants
#define B_      32
#define C_      512
#define HW_     4096            // 64*64
#define NPIX    (B_ * HW_)      // 131072
#define M_      1024
#define THRESH  0.8f
#define MSCALE  16.0f           // fp8 scale applied to normalized memory rows
#define NTILES  (NPIX / 64)     // 2048
#define GRID_P  444             // 148 SMs * 3 CTAs

// ---------------------------------------------------------------------------
// Device scratch (no cudaMalloc allowed)
// ---------------------------------------------------------------------------
__device__ uint8_t g_mem8[M_ * C_];     // normalized memory * 16, e4m3
__device__ int     g_tile_ctr;          // persistent-kernel work counter

__device__ __forceinline__ uint32_t smem_u32(const void* p) {
    uint32_t a;
    asm("{ .reg .u64 t; cvta.to.shared.u64 t, %1; cvt.u32.u64 %0, t; }" : "=r"(a) : "l"(p));
    return a;
}

__device__ __forceinline__ void ldsm_x4(uint32_t* r, uint32_t addr) {
    asm volatile("ldmatrix.sync.aligned.m8n8.x4.shared.b16 {%0,%1,%2,%3}, [%4];"
        : "=r"(r[0]), "=r"(r[1]), "=r"(r[2]), "=r"(r[3]) : "r"(addr));
}

__device__ __forceinline__ void mma_fp8(float* d, const uint32_t* a, const uint32_t* b) {
    asm volatile("mma.sync.aligned.m16n8k32.row.col.f32.e4m3.e4m3.f32 "
        "{%0,%1,%2,%3}, {%4,%5,%6,%7}, {%8,%9}, {%0,%1,%2,%3};"
        : "+f"(d[0]), "+f"(d[1]), "+f"(d[2]), "+f"(d[3])
        : "r"(a[0]), "r"(a[1]), "r"(a[2]), "r"(a[3]), "r"(b[0]), "r"(b[1]));
}

// pack 2 floats -> 2 e4m3 bytes (same helper for x and memory: consistent
// k-permutation, dot-invariant).
__device__ __forceinline__ uint16_t pk2(float lo, float hi) {
    uint16_t r;
    asm("cvt.rn.satfinite.e4m3x2.f32 %0, %1, %2;" : "=h"(r) : "f"(hi), "f"(lo));
    return r;
}

__device__ __forceinline__ void cp16(uint32_t dst, const void* src) {
    asm volatile("cp.async.cg.shared.global [%0], [%1], 16;" :: "r"(dst), "l"(src));
}
#define CP_COMMIT() asm volatile("cp.async.commit_group;" ::: "memory")
#define CP_WAIT0()  asm volatile("cp.async.wait_group 0;" ::: "memory")

// ---------------------------------------------------------------------------
// Kernel 0: normalize memory rows -> e4m3 (scaled by 16); resets tile counter.
// ---------------------------------------------------------------------------
__global__ void norm_mem_kernel(const float* __restrict__ mem) {
    int row = blockIdx.x;
    int t   = threadIdx.x;   // 128 threads, 4 floats each
    if (row == 0 && t == 0) g_tile_ctr = 0;
    const float4* r = (const float4*)(mem + (size_t)row * C_);
    float4 v = r[t];
    float ss = v.x * v.x + v.y * v.y + v.z * v.z + v.w * v.w;
#pragma unroll
    for (int o = 16; o; o >>= 1) ss += __shfl_xor_sync(0xffffffffu, ss, o);
    __shared__ float ws[4];
    if ((t & 31) == 0) ws[t >> 5] = ss;
    __syncthreads();
    float tot = ws[0] + ws[1] + ws[2] + ws[3];
    float inv = MSCALE / fmaxf(sqrtf(tot), 1e-12f);
    uint16_t a = pk2(v.x * inv, v.y * inv);
    uint16_t b = pk2(v.z * inv, v.w * inv);
    ((uint32_t*)(g_mem8 + (size_t)row * C_))[t] = (uint32_t)a | ((uint32_t)b << 16);
}

// ---------------------------------------------------------------------------
// Kernel 1: PERSISTENT fully-fused fp8 pipeline, 3 CTAs/SM, 444 CTAs total.
// Each CTA loops over 64-pixel tiles from an atomic counter. Per tile:
// prologue (x transpose + e4m3 + exact fp32 norm), fp8 QMMA GEMM over 8
// N-tiles of 128 memory rows with k=128 B chunks double-buffered via
// cp.async, fused argmax, masked channel-major STG.128 output.
// ---------------------------------------------------------------------------
#define A_PITCH    528
#define B_PITCH    144
#define OFF_B      33792         // 64 * 528
#define B_CHUNK    18432         // 128 * 144
#define OFF_REDV   70656         // OFF_B + 2*B_CHUNK
#define OFF_REDI   71680
#define OFF_PN     72704         // 64 floats
#define OFF_SEL    72960         // 64 ints
#define OFF_TILE   73216         // 1 int (tile broadcast)
#define SMEM_BYTES 73248

__global__ __launch_bounds__(256, 3) void sim_fused_kernel(
    const float* __restrict__ x,
    const float* __restrict__ memf,
    float* __restrict__ out
) {
    extern __shared__ char smem[];
    uint32_t sb = smem_u32(smem);
    float* redv = (float*)(smem + OFF_REDV);   // [64][4]
    int*   redi = (int*)(smem + OFF_REDI);     // [64][4]
    float* pn   = (float*)(smem + OFF_PN);     // [64]
    int*   ssel = (int*)(smem + OFF_SEL);      // [64]
    int*   tsh  = (int*)(smem + OFF_TILE);

    int t    = threadIdx.x;
    int lane = t & 31;
    int w    = t >> 5;
    int wr   = w & 1;      // pixel half (32 px)
    int wc   = w >> 1;     // m quarter (32 m)

    // ---- tile-invariant addressing (hoisted) ----
    uint32_t aAddr[2];
#pragma unroll
    for (int i = 0; i < 2; i++)
        aAddr[i] = sb + (uint32_t)(wr * 32 + i * 16 + (lane & 15)) * A_PITCH
                      + (uint32_t)(lane >> 4) * 16u;
    uint32_t bAddr[2];
#pragma unroll
    for (int jp = 0; jp < 2; jp++)
        bAddr[jp] = sb + OFF_B
                  + (uint32_t)(wc * 32 + (2 * jp + (lane >> 4)) * 8 + (lane & 7)) * B_PITCH
                  + (uint32_t)((lane >> 3) & 1) * 16u;

    // per-thread loadB offsets (m = row, q = quad) hoisted
    // idx pattern: idx = t + i*256, m = idx>>3, q = idx&7
    // B chunk loader via cp.async: rows nt*128..+127, k bytes kc*128..+127
    auto loadB = [&](int nt, int kc, int buf) {
        const char* bsrc = (const char*)g_mem8 + (size_t)(nt * 128) * C_ + kc * 128;
        uint32_t bbm = sb + OFF_B + (uint32_t)buf * B_CHUNK;
#pragma unroll
        for (int i = 0; i < 4; i++) {
            int idx = t + i * 256;           // 0..1023 quads (8 per row)
            int m = idx >> 3;
            int q = idx & 7;
            cp16(bbm + (uint32_t)(m * B_PITCH + q * 16),
                 bsrc + (size_t)m * C_ + q * 16);
        }
        CP_COMMIT();
    };

    // ================= PERSISTENT TILE LOOP ================================
    for (;;) {
        if (t == 0) *tsh = atomicAdd(&g_tile_ctr, 1);
        __syncthreads();
        int tile = *tsh;
        if (tile >= NTILES) break;

        int pix0 = tile * 64;
        int b    = pix0 >> 12;
        int hw0  = pix0 & (HW_ - 1);

        // ---- preload B chunk 0 into buf0 (flies under the prologue) ----
        loadB(0, 0, 0);

        // ============ PROLOGUE: x -> A tile (transpose + e4m3 + norm) ======
        // Staging lives in B buf1 (18.4KB >= 64*65*4 = 16.6KB).
        {
            float* stage = (float*)(smem + OFF_B + B_CHUNK);   // [64][65] floats
            int hwi = t & 63;
            int cl  = t >> 6;              // 0..3
            int px  = t >> 2;              // 0..63
            int ch  = (t & 3) * 16;        // 16-c slice within 64-c sub-tile
            float ss = 0.f;
            const float* xb = x + (size_t)b * C_ * HW_ + hw0;

            for (int ct = 0; ct < 8; ct++) {
                const float* src = xb + (size_t)(ct * 64) * HW_;
#pragma unroll
                for (int i = 0; i < 16; i++) {
                    stage[(cl + i * 4) * 65 + hwi] = src[(size_t)(cl + i * 4) * HW_ + hwi];
                }
                __syncthreads();
                uint16_t h8[8];
#pragma unroll
                for (int j = 0; j < 8; j++) {
                    float a  = stage[(ch + 2 * j) * 65 + px];
                    float c2 = stage[(ch + 2 * j + 1) * 65 + px];
                    ss += a * a + c2 * c2;
                    h8[j] = pk2(a, c2);
                }
                uint4 r4;
                r4.x = (uint32_t)h8[0] | ((uint32_t)h8[1] << 16);
                r4.y = (uint32_t)h8[2] | ((uint32_t)h8[3] << 16);
                r4.z = (uint32_t)h8[4] | ((uint32_t)h8[5] << 16);
                r4.w = (uint32_t)h8[6] | ((uint32_t)h8[7] << 16);
                *(uint4*)(smem + px * A_PITCH + ct * 64 + ch) = r4;
                __syncthreads();
            }
            ss += __shfl_xor_sync(0xffffffffu, ss, 1);
            ss += __shfl_xor_sync(0xffffffffu, ss, 2);
            if ((t & 3) == 0) pn[px] = ss;
        }

        // ============ MAINLOOP: fp8 QMMA GEMM + argmax ======================
        float bestv[2][2];
        int   besti[2][2];
#pragma unroll
        for (int i = 0; i < 2; i++) {
            bestv[i][0] = -1e30f; bestv[i][1] = -1e30f;
            besti[i][0] = 0;      besti[i][1] = 0;
        }

        for (int nt = 0; nt < 8; nt++) {
            float acc[2][4][4];
#pragma unroll
            for (int i = 0; i < 2; i++)
#pragma unroll
                for (int j = 0; j < 4; j++)
#pragma unroll
                    for (int r = 0; r < 4; r++) acc[i][j][r] = 0.f;

            for (int kc = 0; kc < 4; kc++) {          // 4 chunks of k=128
                CP_WAIT0();        // chunk kc fully arrived
                __syncthreads();   // visible everywhere; compute(kc-1) done
                {
                    int nkc = kc + 1, nnt = nt;
                    if (nkc == 4) { nkc = 0; nnt = nt + 1; }
                    if (nnt < 8) loadB(nnt, nkc, (kc + 1) & 1);
                }
                uint32_t bufOff = (uint32_t)((kc & 1) * B_CHUNK);
                uint32_t kcOff  = (uint32_t)(kc * 128);   // 128 fp8 bytes/chunk
#pragma unroll
                for (int ks = 0; ks < 4; ks++) {
                    uint32_t ko = (uint32_t)(ks * 32);    // one k32 step
                    uint32_t af[2][4];
#pragma unroll
                    for (int i = 0; i < 2; i++)
                        ldsm_x4(af[i], aAddr[i] + kcOff + ko);
                    uint32_t bfr[2][4];
#pragma unroll
                    for (int jp = 0; jp < 2; jp++)
                        ldsm_x4(bfr[jp], bAddr[jp] + bufOff + ko);
#pragma unroll
                    for (int i = 0; i < 2; i++)
#pragma unroll
                        for (int j = 0; j < 4; j++)
                            mma_fp8(acc[i][j], af[i], &bfr[j >> 1][(j & 1) * 2]);
                }
            }

            // fold N-tile into running argmax (first-max tie-break)
#pragma unroll
            for (int i = 0; i < 2; i++)
#pragma unroll
                for (int rp = 0; rp < 2; rp++)
#pragma unroll
                    for (int j = 0; j < 4; j++)
#pragma unroll
                        for (int c = 0; c < 2; c++) {
                            float v = acc[i][j][rp * 2 + c];
                            if (v > bestv[i][rp]) {
                                bestv[i][rp] = v;
                                besti[i][rp] = nt * 128 + wc * 32 + j * 8 + (lane & 3) * 2 + c;
                            }
                        }
        }

        // ============ EPILOGUE: reductions + selection ======================
#pragma unroll
        for (int i = 0; i < 2; i++)
#pragma unroll
            for (int rp = 0; rp < 2; rp++) {
                float v = bestv[i][rp];
                int   ix = besti[i][rp];
#pragma unroll
                for (int off = 1; off <= 2; off <<= 1) {
                    float ov = __shfl_xor_sync(0xffffffffu, v, off);
                    int   oi = __shfl_xor_sync(0xffffffffu, ix, off);
                    if (ov > v || (ov == v && oi < ix)) { v = ov; ix = oi; }
                }
                if ((lane & 3) == 0) {
                    int row = wr * 32 + i * 16 + (lane >> 2) + rp * 8;
                    redv[row * 4 + wc] = v;
                    redi[row * 4 + wc] = ix;
                }
            }
        __syncthreads();
        if (t < 64) {
            float bv = redv[t * 4];
            int   bi = redi[t * 4];
#pragma unroll
            for (int j = 1; j < 4; j++) {
                float v = redv[t * 4 + j];
                if (v > bv) { bv = v; bi = redi[t * 4 + j]; }
            }
            float n2 = pn[t];
            // dot_q ~ 16 * (x . m_hat); fire iff dot_q > 0.8 * 16 * ||x||
            ssel[t] = (bv > (THRESH * MSCALE) * sqrtf(n2)) ? bi : -1;
        }
        __syncthreads();

        // ============ OUTPUT: masked gather, channel-major STG.128 ==========
        {
            int q4 = (t & 15) * 4;           // pixel quad
            int c0 = t >> 4;                 // 0..15
            int s0 = ssel[q4 + 0];
            int s1 = ssel[q4 + 1];
            int s2 = ssel[q4 + 2];
            int s3 = ssel[q4 + 3];
            const float* mr0 = memf + (size_t)(s0 < 0 ? 0 : s0) * C_;
            const float* mr1 = memf + (size_t)(s1 < 0 ? 0 : s1) * C_;
            const float* mr2 = memf + (size_t)(s2 < 0 ? 0 : s2) * C_;
            const float* mr3 = memf + (size_t)(s3 < 0 ? 0 : s3) * C_;
            float* ob = out + ((size_t)b * C_) * HW_ + hw0 + q4;
#pragma unroll 8
            for (int i = 0; i < 32; i++) {
                int c = c0 + i * 16;
                float4 v;
                v.x = (s0 >= 0) ? mr0[c] : 0.f;
                v.y = (s1 >= 0) ? mr1[c] : 0.f;
                v.z = (s2 >= 0) ? mr2[c] : 0.f;
                v.w = (s3 >= 0) ? mr3[c] : 0.f;
                *(float4*)(ob + (size_t)c * HW_) = v;
            }
        }
        __syncthreads();   // all threads done with ssel/pn before next tile
    }
}

// ---------------------------------------------------------------------------
extern "C" void kernel_launch(void* const* d_in, const int* in_sizes, int n_in,
                              void* d_out, int out_size) {
    const float* x   = (const float*)d_in[0];   // 32*512*64*64
    const float* mem = (const float*)d_in[1];   // 1024*512
    float* out = (float*)d_out;

    cudaFuncSetAttribute(sim_fused_kernel,
                         cudaFuncAttributeMaxDynamicSharedMemorySize, SMEM_BYTES);

    norm_mem_kernel<<<M_, 128>>>(mem);
    sim_fused_kernel<<<GRID_P, 256, SMEM_BYTES>>>(x, mem, out);
}

// round 15
// speedup vs baseline: 1.3562x; 1.0272x over previous
#include <cuda_runtime.h>
#include <cuda_bf16.h>
#include <cstdint>

// Problem constants
#define B_      32
#define C_      512
#define HW_     4096            // 64*64
#define NPIX    (B_ * HW_)      // 131072
#define M_      1024
#define THRESH  0.8f
#define MSCALE  16.0f           // fp8 scale applied to normalized memory rows
#define NTILES  (NPIX / 64)     // 2048
#define GRID_P  444             // 148 SMs * 3 CTAs

// ---------------------------------------------------------------------------
// Device scratch (no cudaMalloc allowed)
// ---------------------------------------------------------------------------
__device__ uint8_t g_mem8[M_ * C_];     // normalized memory * 16, e4m3
__device__ int     g_tile_ctr;          // persistent-kernel work counter

__device__ __forceinline__ uint32_t smem_u32(const void* p) {
    uint32_t a;
    asm("{ .reg .u64 t; cvta.to.shared.u64 t, %1; cvt.u32.u64 %0, t; }" : "=r"(a) : "l"(p));
    return a;
}

__device__ __forceinline__ void ldsm_x4(uint32_t* r, uint32_t addr) {
    asm volatile("ldmatrix.sync.aligned.m8n8.x4.shared.b16 {%0,%1,%2,%3}, [%4];"
        : "=r"(r[0]), "=r"(r[1]), "=r"(r[2]), "=r"(r[3]) : "r"(addr));
}

__device__ __forceinline__ void mma_fp8(float* d, const uint32_t* a, const uint32_t* b) {
    asm volatile("mma.sync.aligned.m16n8k32.row.col.f32.e4m3.e4m3.f32 "
        "{%0,%1,%2,%3}, {%4,%5,%6,%7}, {%8,%9}, {%0,%1,%2,%3};"
        : "+f"(d[0]), "+f"(d[1]), "+f"(d[2]), "+f"(d[3])
        : "r"(a[0]), "r"(a[1]), "r"(a[2]), "r"(a[3]), "r"(b[0]), "r"(b[1]));
}

// pack 2 floats -> 2 e4m3 bytes (same helper for x and memory: consistent
// k-permutation, dot-invariant). lo -> low byte, hi -> high byte.
__device__ __forceinline__ uint16_t pk2(float lo, float hi) {
    uint16_t r;
    asm("cvt.rn.satfinite.e4m3x2.f32 %0, %1, %2;" : "=h"(r) : "f"(hi), "f"(lo));
    return r;
}

__device__ __forceinline__ void cp16(uint32_t dst, const void* src) {
    asm volatile("cp.async.cg.shared.global [%0], [%1], 16;" :: "r"(dst), "l"(src));
}
#define CP_COMMIT() asm volatile("cp.async.commit_group;" ::: "memory")
#define CP_WAIT0()  asm volatile("cp.async.wait_group 0;" ::: "memory")
#define CP_WAIT1()  asm volatile("cp.async.wait_group 1;" ::: "memory")

// ---------------------------------------------------------------------------
// Kernel 0: normalize memory rows -> e4m3 (scaled by 16); resets tile counter.
// ---------------------------------------------------------------------------
__global__ void norm_mem_kernel(const float* __restrict__ mem) {
    int row = blockIdx.x;
    int t   = threadIdx.x;   // 128 threads, 4 floats each
    if (row == 0 && t == 0) g_tile_ctr = 0;
    const float4* r = (const float4*)(mem + (size_t)row * C_);
    float4 v = r[t];
    float ss = v.x * v.x + v.y * v.y + v.z * v.z + v.w * v.w;
#pragma unroll
    for (int o = 16; o; o >>= 1) ss += __shfl_xor_sync(0xffffffffu, ss, o);
    __shared__ float ws[4];
    if ((t & 31) == 0) ws[t >> 5] = ss;
    __syncthreads();
    float tot = ws[0] + ws[1] + ws[2] + ws[3];
    float inv = MSCALE / fmaxf(sqrtf(tot), 1e-12f);
    uint16_t a = pk2(v.x * inv, v.y * inv);
    uint16_t b = pk2(v.z * inv, v.w * inv);
    ((uint32_t*)(g_mem8 + (size_t)row * C_))[t] = (uint32_t)a | ((uint32_t)b << 16);
}

// ---------------------------------------------------------------------------
// Kernel 1: PERSISTENT fully-fused fp8 pipeline, 3 CTAs/SM, 444 CTAs.
// Per tile: cp.async double-buffered transpose prologue (x -> e4m3 A tile +
// exact fp32 norms), fp8 QMMA GEMM (8 N-tiles x 4 k128-chunks, double-buffered
// cp.async B), fused argmax. Output of tile T is deferred into tile T+1's
// async prologue window (cross-tile software pipeline).
// ---------------------------------------------------------------------------
#define A_PITCH    528
#define B_PITCH    144
#define OFF_B      33792         // 64 * 528
#define B_CHUNK    18432         // 128 * 144
#define STG_PITCH  272           // 68 floats, 16B aligned
#define STG_SZ     8704          // 32 * 272
#define OFF_REDV   70656         // OFF_B + 2*B_CHUNK
#define OFF_REDI   71680
#define OFF_PSUM   72704         // [64][4] float partial norms
#define OFF_SEL    73728         // 64 ints
#define OFF_TILE   73984
#define SMEM_BYTES 74112

__global__ __launch_bounds__(256, 3) void sim_fused_kernel(
    const float* __restrict__ x,
    const float* __restrict__ memf,
    float* __restrict__ out
) {
    extern __shared__ char smem[];
    uint32_t sb = smem_u32(smem);
    float* redv = (float*)(smem + OFF_REDV);   // [64][4]
    int*   redi = (int*)(smem + OFF_REDI);     // [64][4]
    float* psum = (float*)(smem + OFF_PSUM);   // [64][4]
    int*   ssel = (int*)(smem + OFF_SEL);      // [64]
    int*   tsh  = (int*)(smem + OFF_TILE);

    int t    = threadIdx.x;
    int lane = t & 31;
    int w    = t >> 5;
    int wr   = w & 1;      // pixel half (32 px)
    int wc   = w >> 1;     // m quarter (32 m)

    // ---- tile-invariant addressing (hoisted) ----
    uint32_t aAddr[2];
#pragma unroll
    for (int i = 0; i < 2; i++)
        aAddr[i] = sb + (uint32_t)(wr * 32 + i * 16 + (lane & 15)) * A_PITCH
                      + (uint32_t)(lane >> 4) * 16u;
    uint32_t bAddr[2];
#pragma unroll
    for (int jp = 0; jp < 2; jp++)
        bAddr[jp] = sb + OFF_B
                  + (uint32_t)(wc * 32 + (2 * jp + (lane >> 4)) * 8 + (lane & 7)) * B_PITCH
                  + (uint32_t)((lane >> 3) & 1) * 16u;

    // B chunk loader: rows nt*128..+127, k bytes kc*128..+127
    auto loadB = [&](int nt, int kc, int buf) {
        const char* bsrc = (const char*)g_mem8 + (size_t)(nt * 128) * C_ + kc * 128;
        uint32_t bbm = sb + OFF_B + (uint32_t)buf * B_CHUNK;
#pragma unroll
        for (int i = 0; i < 4; i++) {
            int idx = t + i * 256;           // 0..1023 quads (8 per row)
            int m = idx >> 3;
            int q = idx & 7;
            cp16(bbm + (uint32_t)(m * B_PITCH + q * 16),
                 bsrc + (size_t)m * C_ + q * 16);
        }
        CP_COMMIT();
    };

    int pb = -1, phw0 = 0;     // deferred-output tile coords

    // ================= PERSISTENT TILE LOOP ================================
    for (;;) {
        if (t == 0) *tsh = atomicAdd(&g_tile_ctr, 1);
        __syncthreads();
        int tile = *tsh;
        if (tile >= NTILES) break;

        int pix0 = tile * 64;
        int b    = pix0 >> 12;
        int hw0  = pix0 & (HW_ - 1);
        const char* xb = (const char*)(x + (size_t)b * C_ * HW_ + hw0);

        // stage loader: 32 channels (sub-tile h) into stage buffer v
        auto loadStage = [&](int h, int v) {
            const char* src = xb + (size_t)(h * 32) * (HW_ * 4);
            uint32_t st = sb + OFF_B + B_CHUNK + (uint32_t)v * STG_SZ;
#pragma unroll
            for (int i = 0; i < 2; i++) {
                int idx = t + i * 256;       // 0..511 quads (16 per 32-row)
                int row = idx >> 4;
                int qc  = idx & 15;
                cp16(st + (uint32_t)(row * STG_PITCH + qc * 16),
                     src + (size_t)row * (HW_ * 4) + qc * 16);
            }
            CP_COMMIT();
        };

        // ---- issue async work first: B chunk 0, stage 0, stage 1 ----
        loadB(0, 0, 0);
        loadStage(0, 0);
        loadStage(1, 1);

        // ---- DEFERRED OUTPUT for previous tile (hides under cp.async) ----
        if (pb >= 0) {
            int q4 = (t & 15) * 4;           // pixel quad
            int c0 = t >> 4;                 // 0..15
            int s0 = ssel[q4 + 0];
            int s1 = ssel[q4 + 1];
            int s2 = ssel[q4 + 2];
            int s3 = ssel[q4 + 3];
            const float* mr0 = memf + (size_t)(s0 < 0 ? 0 : s0) * C_;
            const float* mr1 = memf + (size_t)(s1 < 0 ? 0 : s1) * C_;
            const float* mr2 = memf + (size_t)(s2 < 0 ? 0 : s2) * C_;
            const float* mr3 = memf + (size_t)(s3 < 0 ? 0 : s3) * C_;
            float* ob = out + ((size_t)pb * C_) * HW_ + phw0 + q4;
#pragma unroll 8
            for (int i = 0; i < 32; i++) {
                int c = c0 + i * 16;
                float4 v;
                v.x = (s0 >= 0) ? mr0[c] : 0.f;
                v.y = (s1 >= 0) ? mr1[c] : 0.f;
                v.z = (s2 >= 0) ? mr2[c] : 0.f;
                v.w = (s3 >= 0) ? mr3[c] : 0.f;
                *(float4*)(ob + (size_t)c * HW_) = v;
            }
        }

        // ============ PROLOGUE: staged transpose + e4m3 + norm ==============
        {
            int px = t & 63;
            int rd = t >> 6;               // channel octet within 32-c stage
            float ss = 0.f;
            for (int h = 0; h < 16; h++) {
                CP_WAIT1();                // stage h arrived (h+1 may fly)
                __syncthreads();
                const float* stg = (const float*)(smem + OFF_B + B_CHUNK
                                                  + (h & 1) * STG_SZ);
                uint16_t h4[4];
#pragma unroll
                for (int j = 0; j < 4; j++) {
                    float a  = stg[(rd * 8 + 2 * j) * 68 + px];
                    float c2 = stg[(rd * 8 + 2 * j + 1) * 68 + px];
                    ss += a * a + c2 * c2;
                    h4[j] = pk2(a, c2);
                }
                uint2 r2;
                r2.x = (uint32_t)h4[0] | ((uint32_t)h4[1] << 16);
                r2.y = (uint32_t)h4[2] | ((uint32_t)h4[3] << 16);
                *(uint2*)(smem + px * A_PITCH + h * 32 + rd * 8) = r2;
                __syncthreads();           // stage h fully consumed
                if (h + 2 < 16) loadStage(h + 2, h & 1);
            }
            psum[px * 4 + rd] = ss;
        }

        // ============ MAINLOOP: fp8 QMMA GEMM + argmax ======================
        float bestv[2][2];
        int   besti[2][2];
#pragma unroll
        for (int i = 0; i < 2; i++) {
            bestv[i][0] = -1e30f; bestv[i][1] = -1e30f;
            besti[i][0] = 0;      besti[i][1] = 0;
        }

        for (int nt = 0; nt < 8; nt++) {
            float acc[2][4][4];
#pragma unroll
            for (int i = 0; i < 2; i++)
#pragma unroll
                for (int j = 0; j < 4; j++)
#pragma unroll
                    for (int r = 0; r < 4; r++) acc[i][j][r] = 0.f;

            for (int kc = 0; kc < 4; kc++) {          // 4 chunks of k=128
                CP_WAIT0();        // chunk kc fully arrived
                __syncthreads();   // visible everywhere; compute(kc-1) done
                {
                    int nkc = kc + 1, nnt = nt;
                    if (nkc == 4) { nkc = 0; nnt = nt + 1; }
                    if (nnt < 8) loadB(nnt, nkc, (kc + 1) & 1);
                }
                uint32_t bufOff = (uint32_t)((kc & 1) * B_CHUNK);
                uint32_t kcOff  = (uint32_t)(kc * 128);   // 128 fp8 bytes/chunk
#pragma unroll
                for (int ks = 0; ks < 4; ks++) {
                    uint32_t ko = (uint32_t)(ks * 32);    // one k32 step
                    uint32_t af[2][4];
#pragma unroll
                    for (int i = 0; i < 2; i++)
                        ldsm_x4(af[i], aAddr[i] + kcOff + ko);
                    uint32_t bfr[2][4];
#pragma unroll
                    for (int jp = 0; jp < 2; jp++)
                        ldsm_x4(bfr[jp], bAddr[jp] + bufOff + ko);
#pragma unroll
                    for (int i = 0; i < 2; i++)
#pragma unroll
                        for (int j = 0; j < 4; j++)
                            mma_fp8(acc[i][j], af[i], &bfr[j >> 1][(j & 1) * 2]);
                }
            }

            // fold N-tile into running argmax (first-max tie-break)
#pragma unroll
            for (int i = 0; i < 2; i++)
#pragma unroll
                for (int rp = 0; rp < 2; rp++)
#pragma unroll
                    for (int j = 0; j < 4; j++)
#pragma unroll
                        for (int c = 0; c < 2; c++) {
                            float v = acc[i][j][rp * 2 + c];
                            if (v > bestv[i][rp]) {
                                bestv[i][rp] = v;
                                besti[i][rp] = nt * 128 + wc * 32 + j * 8 + (lane & 3) * 2 + c;
                            }
                        }
        }

        // ============ EPILOGUE: reductions + selection ======================
#pragma unroll
        for (int i = 0; i < 2; i++)
#pragma unroll
            for (int rp = 0; rp < 2; rp++) {
                float v = bestv[i][rp];
                int   ix = besti[i][rp];
#pragma unroll
                for (int off = 1; off <= 2; off <<= 1) {
                    float ov = __shfl_xor_sync(0xffffffffu, v, off);
                    int   oi = __shfl_xor_sync(0xffffffffu, ix, off);
                    if (ov > v || (ov == v && oi < ix)) { v = ov; ix = oi; }
                }
                if ((lane & 3) == 0) {
                    int row = wr * 32 + i * 16 + (lane >> 2) + rp * 8;
                    redv[row * 4 + wc] = v;
                    redi[row * 4 + wc] = ix;
                }
            }
        __syncthreads();
        if (t < 64) {
            float bv = redv[t * 4];
            int   bi = redi[t * 4];
#pragma unroll
            for (int j = 1; j < 4; j++) {
                float v = redv[t * 4 + j];
                if (v > bv) { bv = v; bi = redi[t * 4 + j]; }
            }
            float n2 = psum[t * 4] + psum[t * 4 + 1] + psum[t * 4 + 2] + psum[t * 4 + 3];
            // dot_q ~ 16 * (x . m_hat); fire iff dot_q > 0.8 * 16 * ||x||
            ssel[t] = (bv > (THRESH * MSCALE) * sqrtf(n2)) ? bi : -1;
        }
        __syncthreads();

        pb = b; phw0 = hw0;    // defer output into next tile's async window
    }

    // ---- flush last tile's output ----
    if (pb >= 0) {
        int q4 = (t & 15) * 4;
        int c0 = t >> 4;
        int s0 = ssel[q4 + 0];
        int s1 = ssel[q4 + 1];
        int s2 = ssel[q4 + 2];
        int s3 = ssel[q4 + 3];
        const float* mr0 = memf + (size_t)(s0 < 0 ? 0 : s0) * C_;
        const float* mr1 = memf + (size_t)(s1 < 0 ? 0 : s1) * C_;
        const float* mr2 = memf + (size_t)(s2 < 0 ? 0 : s2) * C_;
        const float* mr3 = memf + (size_t)(s3 < 0 ? 0 : s3) * C_;
        float* ob = out + ((size_t)pb * C_) * HW_ + phw0 + q4;
#pragma unroll 8
        for (int i = 0; i < 32; i++) {
            int c = c0 + i * 16;
            float4 v;
            v.x = (s0 >= 0) ? mr0[c] : 0.f;
            v.y = (s1 >= 0) ? mr1[c] : 0.f;
            v.z = (s2 >= 0) ? mr2[c] : 0.f;
            v.w = (s3 >= 0) ? mr3[c] : 0.f;
            *(float4*)(ob + (size_t)c * HW_) = v;
        }
    }
}

// ---------------------------------------------------------------------------
extern "C" void kernel_launch(void* const* d_in, const int* in_sizes, int n_in,
                              void* d_out, int out_size) {
    const float* x   = (const float*)d_in[0];   // 32*512*64*64
    const float* mem = (const float*)d_in[1];   // 1024*512
    float* out = (float*)d_out;

    cudaFuncSetAttribute(sim_fused_kernel,
                         cudaFuncAttributeMaxDynamicSharedMemorySize, SMEM_BYTES);

    norm_mem_kernel<<<M_, 128>>>(mem);
    sim_fused_kernel<<<GRID_P, 256, SMEM_BYTES>>>(x, mem, out);
}